// round 15
// baseline (speedup 1.0000x reference)
#include <cuda_runtime.h>
#include <math.h>

#define NB 16
#define NT 50
#define NA 5
#define NH 128
#define NW 128
#define NC 20
#define CH 26
#define NTGT (NB*NT)            /* 800 */
#define TOTAL (NB*NA*NH*NW)     /* 1310720 */
#define IGN_CAP (NB*NT*NA)      /* 4000 */

#define GRID_X   148
#define BLOCK_X  768
#define WARPS_PB (BLOCK_X/32)                /* 24 */
#define NWARPS   (GRID_X*WARPS_PB)           /* 3552 */
#define NTHREADS (GRID_X*BLOCK_X)            /* 113664 */
#define NF4      ((TOTAL*CH)/4)              /* 8519680 float4s */
#define CHUNK_F4 416                         /* 32 lanes x 13 f4 = 64 cells */
#define NCHUNKS  (NF4/CHUNK_F4)              /* 20480, exact */
#define TSTRIDE  142                         /* spread 800 targets over threads */

// ---------------- device-global state (zero-initialized at module load) ------
// Replay determinism: every field is either fully overwritten each launch or
// reset by the cleanup phase at the end of the last block.
__device__ int    g_winner[TOTAL];     // 0 = empty, else (ti+1) of owning target
__device__ int    g_ign_grid[TOTAL];   // 0/1 dedup grid for ignore cells
__device__ int    g_ign_list[IGN_CAP];
__device__ int    g_ign_count;         // reset in cleanup
__device__ unsigned int g_bar;         // arrival counter, reset in cleanup
__device__ double g_partials[GRID_X];  // fully overwritten every launch

__device__ int    g_t_cell[NTGT];
__device__ int    g_t_valid[NTGT];
__device__ int    g_t_lab[NTGT];
__device__ float  g_t_tx[NTGT], g_t_ty[NTGT], g_t_tw[NTGT], g_t_th[NTGT], g_t_tr[NTGT];

// ---------------- helpers ----------------------------------------------------
__device__ __forceinline__ float inv_tanhf(float y) {
    if (y <= -1.0f) return -2.0f;
    if (y >=  1.0f) return  2.0f;
    float ys = fminf(fmaxf(y, -1.0f + 1e-6f), 1.0f - 1e-6f);
    return 0.5f * logf((1.0f + ys) / (1.0f - ys));
}

// accurate version (used for the masked BCE term, /≈800 normalizer)
__device__ __forceinline__ float softplusf(float z) {
    return fmaxf(z, 0.0f) + log1pf(expf(-fabsf(z)));
}

// fast version (full-grid sweep, /≈1.3M normalizer; per-elem err ~1e-6)
__device__ __forceinline__ float softplus_fast(float z) {
    return fmaxf(z, 0.0f) + __logf(1.0f + __expf(-fabsf(z)));
}

// ---------------- per-target processing (same math as passing R2 kernel) ------
__device__ void process_target(int t,
                               const float* __restrict__ tgt,
                               const int*   __restrict__ sizes,
                               const float* __restrict__ anch) {
    int b  = t / NT;
    int ti = t - b * NT;
    const float* row = tgt + t * 33;
    const float inv_s = 1.0f / 16.0f;

    float gx = row[0] * inv_s, gy = row[1] * inv_s;
    float gr = row[2];
    float gh = row[3] * inv_s, gw = row[4] * inv_s;
    bool valid = (ti < sizes[b]) && (gw != 0.0f) && (gh != 0.0f);

    int gi = (int)gx; gi = gi < 0 ? 0 : (gi > NW - 1 ? NW - 1 : gi);
    int gj = (int)gy; gj = gj < 0 ? 0 : (gj > NH - 1 ? NH - 1 : gj);

    float cp[8];
#pragma unroll
    for (int k = 0; k < 8; k++) cp[k] = row[5 + k] * inv_s - ((k & 1) ? gy : gx);

    float best = 3.4e38f; int bestn = 0;
#pragma unroll
    for (int a = 0; a < NA; a++) {
        float aw = anch[3*a] * inv_s, ah = anch[3*a+1] * inv_s, ar = anch[3*a+2];
        float cr = cosf(ar), sr = sinf(ar);
        float ap[8] = { -cr*aw, sr*aw, cr*aw, -sr*aw, -sr*ah, -cr*ah, sr*ah, cr*ah };
        float dn = 0.0f;
#pragma unroll
        for (int i = 0; i < 8; i += 2) {
            float dx = cp[i] - ap[i], dy = cp[i+1] - ap[i+1];
            dn += sqrtf(dx*dx + dy*dy);
        }
        float norm = ((gh + gw) * 0.5f + (ah + aw) * 0.5f) * 0.5f;
        float dd = dn / norm;
        float dist = dd * dd;
        if (dist < best) { best = dist; bestn = a; }   // first-occurrence argmin
        if (valid && dist < 0.5f) {
            int cell = ((b * NA + a) * NH + gj) * NW + gi;
            if (atomicExch(&g_ign_grid[cell], 1) == 0) {
                int p = atomicAdd(&g_ign_count, 1);
                g_ign_list[p] = cell;
            }
        }
    }

    const float PI_F = 3.14159265358979323846f;
    float tx = inv_tanhf(gx - ((float)gi + 0.5f));
    float ty = inv_tanhf(gy - ((float)gj + 0.5f));
    float rd = gr - anch[3*bestn+2];
    if (rd >  PI_F) rd -= 2.0f * PI_F;
    else if (rd < -PI_F) rd += 2.0f * PI_F;
    float tr = inv_tanhf(rd / (PI_F * 0.5f));
    float awb = anch[3*bestn] * inv_s, ahb = anch[3*bestn+1] * inv_s;
    float tw = logf(gw / awb + 1e-16f);
    float th = logf(gh / ahb + 1e-16f);

    int lab = 0; float mx = row[13];
#pragma unroll
    for (int c = 1; c < NC; c++) {
        float v = row[13 + c];
        if (v > mx) { mx = v; lab = c; }   // first-occurrence argmax
    }

    int cell = ((b * NA + bestn) * NH + gj) * NW + gi;
    g_t_cell[t]  = cell;
    g_t_valid[t] = valid ? 1 : 0;
    g_t_lab[t]   = lab;
    g_t_tx[t] = tx; g_t_ty[t] = ty; g_t_tw[t] = tw; g_t_th[t] = th; g_t_tr[t] = tr;
    if (valid) atomicMax(&g_winner[cell], ti + 1);   // last-t-wins (XLA scatter dup)
}

// ---------------- fused kernel ------------------------------------------------
__global__ void __launch_bounds__(BLOCK_X, 1)
k_fused(const float* __restrict__ pred,
        const float* __restrict__ tgt,
        const int*   __restrict__ sizes,
        const float* __restrict__ anch,
        float*       __restrict__ out) {
    const int tid  = threadIdx.x;
    const int gt   = blockIdx.x * BLOCK_X + tid;
    const int lane = tid & 31;
    const int wgid = blockIdx.x * WARPS_PB + (tid >> 5);
    __shared__ bool s_is_last;

    // sparse target threads (~5.6 per block): gt = t * TSTRIDE
    {
        int t = gt / TSTRIDE;
        if (t * TSTRIDE == gt && t < NTGT)
            process_target(t, tgt, sizes, anch);
    }

    // ===================== PHASE A: warp-tiled coalesced sweep ===============
    // Warp chunk = 416 consecutive float4s (64 cells). Lane l loads
    // buf[j] = p4[base + l + 32j] (13 coalesced, independent LDG.128s).
    // Since 416 % 13 == 0: q mod 13 = (l + 6j) mod 13 for q = base+l+32j.
    // Conf values live at q%13==0 (comp .x) and q%13==6 (comp .z); each lane
    // owns exactly two: j0 = (2*(l%13))%13 and j6 = (j0+1)%13.
    const float4* __restrict__ p4 = (const float4*)pred;
    const int lm = lane % 13;
    const int j0 = (2 * lm) % 13;
    const int j6 = (j0 + 1) % 13;

    float facc = 0.0f;
    for (int c = wgid; c < NCHUNKS; c += NWARPS) {
        const float4* __restrict__ bp = p4 + (size_t)c * CHUNK_F4 + lane;
        float4 buf[13];
#pragma unroll
        for (int j = 0; j < 13; j++) buf[j] = __ldg(&bp[32 * j]);
        float z0 = 0.0f, z1 = 0.0f;
#pragma unroll
        for (int j = 0; j < 13; j++) {
            if (j == j0) z0 = buf[j].x;
            if (j == j6) z1 = buf[j].z;
        }
        facc += softplus_fast(z0) + softplus_fast(z1);
    }
    double acc = (double)facc;

    // block-reduce the conf partial
#pragma unroll
    for (int o = 16; o > 0; o >>= 1)
        acc += __shfl_down_sync(0xffffffffu, acc, o);
    __shared__ double wsum[WARPS_PB];
    if (lane == 0) wsum[tid >> 5] = acc;
    __syncthreads();
    if (tid == 0) {
        double s = 0.0;
        for (int i = 0; i < WARPS_PB; i++) s += wsum[i];
        g_partials[blockIdx.x] = s;
        // make this block's global writes visible, then arrive (no waiting!)
        __threadfence();
        unsigned int old = atomicAdd(&g_bar, 1u);
        s_is_last = (old == (unsigned)(GRID_X - 1));
    }
    __syncthreads();
    if (!s_is_last) return;          // every block except the LAST one exits

    // ===================== PHASE B (last arriving block) =====================
    __threadfence();                 // acquire: see all blocks' writes

    double sub = 0.0, bcem = 0.0, mse = 0.0, nll = 0.0, sumall = 0.0;
    double mcnt = 0.0, s0 = 0.0;

    // mask cells: loop over targets (800 > 768 threads); only winners compute
    for (int t = tid; t < NTGT; t += BLOCK_X) {
        if (!g_t_valid[t]) continue;
        int cell = g_t_cell[t];
        int ti = t % NT;
        if (g_winner[cell] == ti + 1) {
            const float* p = pred + (size_t)cell * CH;
            float conf = p[0];
            sub  += (double)softplus_fast(conf); // exact cancel vs phase-A sum
            bcem += (double)softplusf(-conf);    // bce(z, t=1), accurate
            float d1 = p[1] - g_t_tx[t];
            float d2 = p[2] - g_t_ty[t];
            float d3 = p[3] - g_t_tr[t];
            float d4 = p[4] - g_t_th[t];
            float d5 = p[5] - g_t_tw[t];
            mse += (double)(d1*d1) + (double)(d2*d2) + (double)(d3*d3)
                 + (double)(d4*d4) + (double)(d5*d5);
            float mmax = p[6];
#pragma unroll
            for (int c = 1; c < NC; c++) mmax = fmaxf(mmax, p[6 + c]);
            float se = 0.0f;
#pragma unroll
            for (int c = 0; c < NC; c++) se += expf(p[6 + c] - mmax);
            nll += (double)(mmax + logf(se) - p[6 + g_t_lab[t]]);
            mcnt += 1.0;
        }
    }

    // ignore cells not covered by a mask cell (S0) — conf sectors are L2-hot
    int icnt = g_ign_count;
    for (int i = tid; i < icnt; i += BLOCK_X) {
        int cell = g_ign_list[i];
        if (g_winner[cell] == 0) {
            s0  += 1.0;
            sub += (double)softplus_fast(__ldg(&pred[(size_t)cell * CH]));
        }
    }

    // pull in the per-block partial sums
    for (int i = tid; i < GRID_X; i += BLOCK_X) sumall += g_partials[i];

    // reduce 7 doubles across the block
    double r[7] = { sub, bcem, mse, nll, sumall, mcnt, s0 };
#pragma unroll
    for (int q = 0; q < 7; q++)
#pragma unroll
        for (int o = 16; o > 0; o >>= 1)
            r[q] += __shfl_down_sync(0xffffffffu, r[q], o);

    __shared__ double sh[7][WARPS_PB];
    if (lane == 0)
#pragma unroll
        for (int q = 0; q < 7; q++) sh[q][tid >> 5] = r[q];
    __syncthreads();

    if (tid == 0) {
        double S = 0, B = 0, E = 0, L = 0, A = 0, M = 0, Z = 0;
        for (int i = 0; i < WARPS_PB; i++) {
            S += sh[0][i]; B += sh[1][i]; E += sh[2][i]; L += sh[3][i];
            A += sh[4][i]; M += sh[5][i]; Z += sh[6][i];
        }
        double nfalse = (double)TOTAL - Z - M;
        double dm = M > 1.0 ? M : 1.0;
        double df = nfalse > 1.0 ? nfalse : 1.0;
        double loss = 1.25 * (A - S) / df   // conf_mask_false BCE
                    + B / dm                // mask BCE
                    + E / dm                // x+y+w+h+r MSE
                    + L / dm;               // class NLL
        out[0] = (float)loss;
    }
    __syncthreads();   // phase-B reads of g_winner done before cleanup writes

    // ===================== CLEANUP (replay determinism) ======================
    for (int t = tid; t < NTGT; t += BLOCK_X)
        g_winner[g_t_cell[t]] = 0;               // superset of touched cells
    for (int i = tid; i < icnt; i += BLOCK_X) g_ign_grid[g_ign_list[i]] = 0;
    if (tid == 0) { g_ign_count = 0; g_bar = 0u; }
}

// ---------------- launch ------------------------------------------------------
extern "C" void kernel_launch(void* const* d_in, const int* in_sizes, int n_in,
                              void* d_out, int out_size) {
    const float* pred  = nullptr;
    const float* tgt   = nullptr;
    const int*   sizes = nullptr;
    const float* anch  = nullptr;
    for (int i = 0; i < n_in; i++) {
        int s = in_sizes[i];
        if      (s == NB * NA * NH * NW * CH) pred  = (const float*)d_in[i];
        else if (s == NB * NT * 33)           tgt   = (const float*)d_in[i];
        else if (s == NB)                     sizes = (const int*)d_in[i];
        else if (s == 15)                     anch  = (const float*)d_in[i];
    }
    (void)out_size;
    k_fused<<<GRID_X, BLOCK_X>>>(pred, tgt, sizes, anch, (float*)d_out);
}

// round 17
// speedup vs baseline: 1.3402x; 1.3402x over previous
#include <cuda_runtime.h>
#include <math.h>

#define NB 16
#define NT 50
#define NA 5
#define NH 128
#define NW 128
#define NC 20
#define CH 26
#define NTGT (NB*NT)            /* 800 */
#define TOTAL (NB*NA*NH*NW)     /* 1310720 */
#define IGN_CAP (NB*NT*NA)      /* 4000 */

#define GRID_X   128
#define BLOCK_X  1024
#define NTHREADS (GRID_X*BLOCK_X)            /* 131072 */
#define NF2      ((TOTAL*CH)/2)              /* 17039360 float2s */
#define NGROUPS  10                          /* 131072*130 == NF2, 130=10*13 */
#define TSTRIDE  163                         /* spread 800 targets over threads */

// ---------------- device-global state (zero-initialized at module load) ------
// Replay determinism: every field is either fully overwritten each launch or
// reset by the cleanup phase at the end of the last block.
__device__ int    g_winner[TOTAL];     // 0 = empty, else (ti+1) of owning target
__device__ int    g_ign_grid[TOTAL];   // 0/1 dedup grid for ignore cells
__device__ int    g_ign_list[IGN_CAP];
__device__ int    g_ign_count;         // reset in cleanup
__device__ unsigned int g_bar;         // arrival counter, reset in cleanup
__device__ double g_partials[GRID_X];  // fully overwritten every launch

__device__ int    g_t_cell[NTGT];
__device__ int    g_t_valid[NTGT];
__device__ int    g_t_lab[NTGT];
__device__ float  g_t_tx[NTGT], g_t_ty[NTGT], g_t_tw[NTGT], g_t_th[NTGT], g_t_tr[NTGT];

// ---------------- helpers ----------------------------------------------------
__device__ __forceinline__ float inv_tanhf(float y) {
    if (y <= -1.0f) return -2.0f;
    if (y >=  1.0f) return  2.0f;
    float ys = fminf(fmaxf(y, -1.0f + 1e-6f), 1.0f - 1e-6f);
    return 0.5f * logf((1.0f + ys) / (1.0f - ys));
}

// accurate version (used for the masked BCE term, /≈800 normalizer)
__device__ __forceinline__ float softplusf(float z) {
    return fmaxf(z, 0.0f) + log1pf(expf(-fabsf(z)));
}

// fast version (full-grid sweep, /≈1.3M normalizer; per-elem err ~1e-6)
__device__ __forceinline__ float softplus_fast(float z) {
    return fmaxf(z, 0.0f) + __logf(1.0f + __expf(-fabsf(z)));
}

// ---------------- per-target processing (same math as passing R2 kernel) ------
__device__ void process_target(int t,
                               const float* __restrict__ tgt,
                               const int*   __restrict__ sizes,
                               const float* __restrict__ anch) {
    int b  = t / NT;
    int ti = t - b * NT;
    const float* row = tgt + t * 33;
    const float inv_s = 1.0f / 16.0f;

    float gx = row[0] * inv_s, gy = row[1] * inv_s;
    float gr = row[2];
    float gh = row[3] * inv_s, gw = row[4] * inv_s;
    bool valid = (ti < sizes[b]) && (gw != 0.0f) && (gh != 0.0f);

    int gi = (int)gx; gi = gi < 0 ? 0 : (gi > NW - 1 ? NW - 1 : gi);
    int gj = (int)gy; gj = gj < 0 ? 0 : (gj > NH - 1 ? NH - 1 : gj);

    float cp[8];
#pragma unroll
    for (int k = 0; k < 8; k++) cp[k] = row[5 + k] * inv_s - ((k & 1) ? gy : gx);

    float best = 3.4e38f; int bestn = 0;
#pragma unroll
    for (int a = 0; a < NA; a++) {
        float aw = anch[3*a] * inv_s, ah = anch[3*a+1] * inv_s, ar = anch[3*a+2];
        float cr = cosf(ar), sr = sinf(ar);
        float ap[8] = { -cr*aw, sr*aw, cr*aw, -sr*aw, -sr*ah, -cr*ah, sr*ah, cr*ah };
        float dn = 0.0f;
#pragma unroll
        for (int i = 0; i < 8; i += 2) {
            float dx = cp[i] - ap[i], dy = cp[i+1] - ap[i+1];
            dn += sqrtf(dx*dx + dy*dy);
        }
        float norm = ((gh + gw) * 0.5f + (ah + aw) * 0.5f) * 0.5f;
        float dd = dn / norm;
        float dist = dd * dd;
        if (dist < best) { best = dist; bestn = a; }   // first-occurrence argmin
        if (valid && dist < 0.5f) {
            int cell = ((b * NA + a) * NH + gj) * NW + gi;
            if (atomicExch(&g_ign_grid[cell], 1) == 0) {
                int p = atomicAdd(&g_ign_count, 1);
                g_ign_list[p] = cell;
            }
        }
    }

    const float PI_F = 3.14159265358979323846f;
    float tx = inv_tanhf(gx - ((float)gi + 0.5f));
    float ty = inv_tanhf(gy - ((float)gj + 0.5f));
    float rd = gr - anch[3*bestn+2];
    if (rd >  PI_F) rd -= 2.0f * PI_F;
    else if (rd < -PI_F) rd += 2.0f * PI_F;
    float tr = inv_tanhf(rd / (PI_F * 0.5f));
    float awb = anch[3*bestn] * inv_s, ahb = anch[3*bestn+1] * inv_s;
    float tw = logf(gw / awb + 1e-16f);
    float th = logf(gh / ahb + 1e-16f);

    int lab = 0; float mx = row[13];
#pragma unroll
    for (int c = 1; c < NC; c++) {
        float v = row[13 + c];
        if (v > mx) { mx = v; lab = c; }   // first-occurrence argmax
    }

    int cell = ((b * NA + bestn) * NH + gj) * NW + gi;
    g_t_cell[t]  = cell;
    g_t_valid[t] = valid ? 1 : 0;
    g_t_lab[t]   = lab;
    g_t_tx[t] = tx; g_t_ty[t] = ty; g_t_tw[t] = tw; g_t_th[t] = th; g_t_tr[t] = tr;
    if (valid) atomicMax(&g_winner[cell], ti + 1);   // last-t-wins (XLA scatter dup)
}

// ---------------- fused kernel ------------------------------------------------
__global__ void __launch_bounds__(BLOCK_X, 1)
k_fused(const float* __restrict__ pred,
        const float* __restrict__ tgt,
        const int*   __restrict__ sizes,
        const float* __restrict__ anch,
        float*       __restrict__ out) {
    const int tid  = threadIdx.x;
    const int gt   = blockIdx.x * BLOCK_X + tid;
    const int lane = tid & 31;
    __shared__ bool s_is_last;

    // sparse target threads (~6 per block): gt = t * TSTRIDE
    {
        int t = gt / TSTRIDE;
        if (t * TSTRIDE == gt && t < NTGT)
            process_target(t, tgt, sizes, anch);
    }

    // ===================== PHASE A: branch-free float2 stream ================
    // NF2 = NTHREADS * 130 exactly: 10 groups of 13 guard-free LDG.64s.
    // Stride NTHREADS ≡ 6 (mod 13) → residues r0+6j cover all of Z13 per
    // group; conf (.x of float2 index ≡ 0 mod 13) appears exactly once per
    // group, at j0 = (2*(gt%13)) % 13. Small 26-reg buffer so ptxas
    // front-batches all 13 loads (MLP_p1 = 13).
    const float2* __restrict__ p2 = (const float2*)pred;
    const int r0 = gt % 13;
    const int j0 = (2 * r0) % 13;

    float facc = 0.0f;
    unsigned int dummy = 0u;       // keeps .y live -> loads can't be narrowed
    const float2* __restrict__ bp = p2 + gt;
#pragma unroll 1
    for (int g = 0; g < NGROUPS; g++) {
        float2 buf[13];
#pragma unroll
        for (int j = 0; j < 13; j++)
            buf[j] = __ldg(&bp[(size_t)(g * 13 + j) * NTHREADS]);
        float z = 0.0f;
#pragma unroll
        for (int j = 0; j < 13; j++) {
            if (j == j0) z = buf[j].x;
            dummy ^= __float_as_uint(buf[j].y);
        }
        facc += softplus_fast(z);
    }
    // never-meaningful: if ever taken, 1e-30f is exactly absorbed by facc
    if (dummy == 0x13572468u) facc += 1e-30f;

    double acc = (double)facc;

    // block-reduce the conf partial
#pragma unroll
    for (int o = 16; o > 0; o >>= 1)
        acc += __shfl_down_sync(0xffffffffu, acc, o);
    __shared__ double wsum[BLOCK_X / 32];
    if (lane == 0) wsum[tid >> 5] = acc;
    __syncthreads();
    if (tid == 0) {
        double s = 0.0;
        for (int i = 0; i < BLOCK_X / 32; i++) s += wsum[i];
        g_partials[blockIdx.x] = s;
        // make this block's global writes visible, then arrive (no waiting!)
        __threadfence();
        unsigned int old = atomicAdd(&g_bar, 1u);
        s_is_last = (old == (unsigned)(GRID_X - 1));
    }
    __syncthreads();
    if (!s_is_last) return;          // every block except the LAST one exits

    // ===================== PHASE B (last arriving block) =====================
    __threadfence();                 // acquire: see all blocks' writes

    double sub = 0.0, bcem = 0.0, mse = 0.0, nll = 0.0, sumall = 0.0;
    double mcnt = 0.0, s0 = 0.0;

    // mask cells: one thread per target; only the winner computes
    if (tid < NTGT && g_t_valid[tid]) {
        int cell = g_t_cell[tid];
        int ti = tid % NT;
        if (g_winner[cell] == ti + 1) {
            const float* p = pred + (size_t)cell * CH;
            float conf = p[0];
            sub  += (double)softplus_fast(conf); // exact cancel vs phase-A sum
            bcem += (double)softplusf(-conf);    // bce(z, t=1), accurate
            float d1 = p[1] - g_t_tx[tid];
            float d2 = p[2] - g_t_ty[tid];
            float d3 = p[3] - g_t_tr[tid];
            float d4 = p[4] - g_t_th[tid];
            float d5 = p[5] - g_t_tw[tid];
            mse += (double)(d1*d1) + (double)(d2*d2) + (double)(d3*d3)
                 + (double)(d4*d4) + (double)(d5*d5);
            float mmax = p[6];
#pragma unroll
            for (int c = 1; c < NC; c++) mmax = fmaxf(mmax, p[6 + c]);
            float se = 0.0f;
#pragma unroll
            for (int c = 0; c < NC; c++) se += expf(p[6 + c] - mmax);
            nll += (double)(mmax + logf(se) - p[6 + g_t_lab[tid]]);
            mcnt = 1.0;
        }
    }

    // ignore cells not covered by a mask cell (S0) — conf sectors are L2-hot
    int icnt = g_ign_count;
    for (int i = tid; i < icnt; i += BLOCK_X) {
        int cell = g_ign_list[i];
        if (g_winner[cell] == 0) {
            s0  += 1.0;
            sub += (double)softplus_fast(__ldg(&pred[(size_t)cell * CH]));
        }
    }

    // pull in the per-block partial sums
    for (int i = tid; i < GRID_X; i += BLOCK_X) sumall += g_partials[i];

    // reduce 7 doubles across the block
    double r[7] = { sub, bcem, mse, nll, sumall, mcnt, s0 };
#pragma unroll
    for (int q = 0; q < 7; q++)
#pragma unroll
        for (int o = 16; o > 0; o >>= 1)
            r[q] += __shfl_down_sync(0xffffffffu, r[q], o);

    __shared__ double sh[7][BLOCK_X / 32];
    if (lane == 0)
#pragma unroll
        for (int q = 0; q < 7; q++) sh[q][tid >> 5] = r[q];
    __syncthreads();

    if (tid == 0) {
        double S = 0, B = 0, E = 0, L = 0, A = 0, M = 0, Z = 0;
        for (int i = 0; i < BLOCK_X / 32; i++) {
            S += sh[0][i]; B += sh[1][i]; E += sh[2][i]; L += sh[3][i];
            A += sh[4][i]; M += sh[5][i]; Z += sh[6][i];
        }
        double nfalse = (double)TOTAL - Z - M;
        double dm = M > 1.0 ? M : 1.0;
        double df = nfalse > 1.0 ? nfalse : 1.0;
        double loss = 1.25 * (A - S) / df   // conf_mask_false BCE
                    + B / dm                // mask BCE
                    + E / dm                // x+y+w+h+r MSE
                    + L / dm;               // class NLL
        out[0] = (float)loss;
    }
    __syncthreads();   // phase-B reads of g_winner done before cleanup writes

    // ===================== CLEANUP (replay determinism) ======================
    if (tid < NTGT) g_winner[g_t_cell[tid]] = 0;   // superset of touched cells
    for (int i = tid; i < icnt; i += BLOCK_X) g_ign_grid[g_ign_list[i]] = 0;
    if (tid == 0) { g_ign_count = 0; g_bar = 0u; }
}

// ---------------- launch ------------------------------------------------------
extern "C" void kernel_launch(void* const* d_in, const int* in_sizes, int n_in,
                              void* d_out, int out_size) {
    const float* pred  = nullptr;
    const float* tgt   = nullptr;
    const int*   sizes = nullptr;
    const float* anch  = nullptr;
    for (int i = 0; i < n_in; i++) {
        int s = in_sizes[i];
        if      (s == NB * NA * NH * NW * CH) pred  = (const float*)d_in[i];
        else if (s == NB * NT * 33)           tgt   = (const float*)d_in[i];
        else if (s == NB)                     sizes = (const int*)d_in[i];
        else if (s == 15)                     anch  = (const float*)d_in[i];
    }
    (void)out_size;
    k_fused<<<GRID_X, BLOCK_X>>>(pred, tgt, sizes, anch, (float*)d_out);
}